// round 1
// baseline (speedup 1.0000x reference)
#include <cuda_runtime.h>
#include <cuda_bf16.h>
#include <math.h>

#define B_SZ   4
#define T_SEQ  1024
#define DIMC   768
#define NH     12
#define DH     64
#define NROWS  (B_SZ * T_SEQ)          // 4096
#define QKV_N  (3 * DIMC)              // 2304

// -------- scratch (static device globals; no allocation) --------
// layout: qkv_c [4096*2304] | qkv_ac [4096*2304] | attn_c [4096*768] |
//         attn_ac [4096*768] | proj_c [4096*768] | proj_ac [4096*768]
__device__ float g_scratch[(size_t)2 * NROWS * QKV_N + (size_t)4 * NROWS * DIMC];

// ============================================================================
// Tiled SGEMM with bias: C[M,N] = A[M,K] @ W[K,N] + bias[N]
// BM=BN=64, BK=16, 256 threads, 4x4 microtile per thread.
// ============================================================================
#define GT   64
#define GBK  16

__global__ void sgemm_bias(const float* __restrict__ A,
                           const float* __restrict__ W,
                           const float* __restrict__ bias,
                           float* __restrict__ C,
                           int M, int N, int K)
{
    __shared__ float As[GBK][GT];   // transposed: As[k][m]
    __shared__ float Bs[GBK][GT];   // Bs[k][n]

    const int tid = threadIdx.x;
    const int tx = tid & 15;        // 0..15 (n groups)
    const int ty = tid >> 4;        // 0..15 (m groups)
    const int m0 = blockIdx.y * GT;
    const int n0 = blockIdx.x * GT;

    float acc[4][4] = {};

    for (int k0 = 0; k0 < K; k0 += GBK) {
        // load A tile (64 rows x 16 k) -> one float4 per thread
        {
            int row = tid >> 2;            // 0..63
            int kk  = (tid & 3) * 4;       // 0,4,8,12
            float4 a = *(const float4*)&A[(size_t)(m0 + row) * K + k0 + kk];
            As[kk + 0][row] = a.x;
            As[kk + 1][row] = a.y;
            As[kk + 2][row] = a.z;
            As[kk + 3][row] = a.w;
            // load B tile (16 k x 64 n) -> one float4 per thread
            int kr = tid >> 4;             // 0..15
            int nn = (tid & 15) * 4;       // 0..60
            *(float4*)&Bs[kr][nn] =
                *(const float4*)&W[(size_t)(k0 + kr) * N + n0 + nn];
        }
        __syncthreads();

#pragma unroll
        for (int k = 0; k < GBK; k++) {
            float4 a = *(float4*)&As[k][ty * 4];
            float4 b = *(float4*)&Bs[k][tx * 4];
            acc[0][0] += a.x * b.x; acc[0][1] += a.x * b.y; acc[0][2] += a.x * b.z; acc[0][3] += a.x * b.w;
            acc[1][0] += a.y * b.x; acc[1][1] += a.y * b.y; acc[1][2] += a.y * b.z; acc[1][3] += a.y * b.w;
            acc[2][0] += a.z * b.x; acc[2][1] += a.z * b.y; acc[2][2] += a.z * b.z; acc[2][3] += a.z * b.w;
            acc[3][0] += a.w * b.x; acc[3][1] += a.w * b.y; acc[3][2] += a.w * b.z; acc[3][3] += a.w * b.w;
        }
        __syncthreads();
    }

    float4 bv = *(const float4*)&bias[n0 + tx * 4];
#pragma unroll
    for (int i = 0; i < 4; i++) {
        int row = m0 + ty * 4 + i;
        float4 out;
        out.x = acc[i][0] + bv.x;
        out.y = acc[i][1] + bv.y;
        out.z = acc[i][2] + bv.z;
        out.w = acc[i][3] + bv.w;
        *(float4*)&C[(size_t)row * N + n0 + tx * 4] = out;
    }
}

// ============================================================================
// Flash-style masked attention.
// qkv: [B*T, 3*DIMC] rows; Q at col h*64, K at 768+h*64, V at 1536+h*64.
// out: [B*T, DIMC] (head-interleaved -> directly consumable by proj GEMM).
// BM=64 query rows per block, BN=32 key rows per tile, 256 threads.
// S microtile 4x2 (ty: 16 m-groups, tx: 16 n-groups); O microtile 4x4 (m,d).
// ============================================================================
#define ABM 64
#define ABN 32
#define QPAD (DH + 4)

__global__ void attn_kernel(const float* __restrict__ qkv,
                            float* __restrict__ outp,
                            int causal)
{
    __shared__ float Qs[ABM][QPAD];
    __shared__ float Ks[ABN][QPAD];
    __shared__ float Vs[ABN][QPAD];
    __shared__ float Ss[ABM][ABN + 1];
    __shared__ float m_row[ABM], l_row[ABM], sc_row[ABM];

    const int b  = blockIdx.z;
    const int h  = blockIdx.y;
    const int m0 = blockIdx.x * ABM;
    const int tid = threadIdx.x;
    const int tx = tid & 15;
    const int ty = tid >> 4;

    const size_t rowstride = QKV_N;
    const float* qbase = qkv + (size_t)b * T_SEQ * QKV_N + h * DH;
    const float* kbase = qbase + DIMC;
    const float* vbase = qbase + 2 * DIMC;

    // load Q tile (scaled by 1/sqrt(64) = 0.125)
#pragma unroll
    for (int i = 0; i < 4; i++) {
        int idx = i * 256 + tid;
        int r  = idx >> 4;
        int d4 = (idx & 15) * 4;
        float4 q = *(const float4*)&qbase[(size_t)(m0 + r) * rowstride + d4];
        Qs[r][d4 + 0] = q.x * 0.125f;
        Qs[r][d4 + 1] = q.y * 0.125f;
        Qs[r][d4 + 2] = q.z * 0.125f;
        Qs[r][d4 + 3] = q.w * 0.125f;
    }
    if (tid < ABM) { m_row[tid] = -INFINITY; l_row[tid] = 0.0f; }
    __syncthreads();

    float o[4][4] = {};

    int n_start, n_end;
    if (causal) { n_start = 0;  n_end = m0 + ABM; }   // keys j <= i
    else        { n_start = m0; n_end = T_SEQ;     }  // keys j >= i

    for (int n0 = n_start; n0 < n_end; n0 += ABN) {
        // load K, V tiles
#pragma unroll
        for (int i = 0; i < 2; i++) {
            int idx = i * 256 + tid;
            int r  = idx >> 4;
            int d4 = (idx & 15) * 4;
            *(float4*)&Ks[r][d4] = *(const float4*)&kbase[(size_t)(n0 + r) * rowstride + d4];
            *(float4*)&Vs[r][d4] = *(const float4*)&vbase[(size_t)(n0 + r) * rowstride + d4];
        }
        __syncthreads();

        // S = Q K^T  (4 rows x 2 key-cols per thread)
        float s[4][2] = {};
#pragma unroll
        for (int d = 0; d < DH; d += 4) {
            float4 k0v = *(float4*)&Ks[tx * 2 + 0][d];
            float4 k1v = *(float4*)&Ks[tx * 2 + 1][d];
#pragma unroll
            for (int i = 0; i < 4; i++) {
                float4 qv = *(float4*)&Qs[ty * 4 + i][d];
                s[i][0] += qv.x * k0v.x + qv.y * k0v.y + qv.z * k0v.z + qv.w * k0v.w;
                s[i][1] += qv.x * k1v.x + qv.y * k1v.y + qv.z * k1v.z + qv.w * k1v.w;
            }
        }
        // mask + store scores
#pragma unroll
        for (int i = 0; i < 4; i++) {
            int gq = m0 + ty * 4 + i;
#pragma unroll
            for (int j = 0; j < 2; j++) {
                int gk = n0 + tx * 2 + j;
                bool ok = causal ? (gk <= gq) : (gk >= gq);
                Ss[ty * 4 + i][tx * 2 + j] = ok ? s[i][j] : -INFINITY;
            }
        }
        __syncthreads();

        // online softmax update (one thread per query row)
        if (tid < ABM) {
            int r = tid;
            float mo = m_row[r];
            float mx = mo;
#pragma unroll
            for (int n = 0; n < ABN; n++) mx = fmaxf(mx, Ss[r][n]);
            float scl, ls = 0.0f;
            if (mx == -INFINITY) {
                scl = 1.0f;
#pragma unroll
                for (int n = 0; n < ABN; n++) Ss[r][n] = 0.0f;
            } else {
                scl = __expf(mo - mx);
#pragma unroll
                for (int n = 0; n < ABN; n++) {
                    float p = __expf(Ss[r][n] - mx);
                    Ss[r][n] = p;
                    ls += p;
                }
            }
            m_row[r]  = mx;
            l_row[r]  = l_row[r] * scl + ls;
            sc_row[r] = scl;
        }
        __syncthreads();

        // rescale O and accumulate P @ V
#pragma unroll
        for (int i = 0; i < 4; i++) {
            float scl = sc_row[ty * 4 + i];
            o[i][0] *= scl; o[i][1] *= scl; o[i][2] *= scl; o[i][3] *= scl;
        }
#pragma unroll
        for (int n = 0; n < ABN; n++) {
            float4 v = *(float4*)&Vs[n][tx * 4];
#pragma unroll
            for (int i = 0; i < 4; i++) {
                float p = Ss[ty * 4 + i][n];
                o[i][0] += p * v.x;
                o[i][1] += p * v.y;
                o[i][2] += p * v.z;
                o[i][3] += p * v.w;
            }
        }
        __syncthreads();
    }

    // normalize and write out, layout [B*T, DIMC] with head offset
#pragma unroll
    for (int i = 0; i < 4; i++) {
        int r = ty * 4 + i;
        float inv = 1.0f / l_row[r];
        float4 res;
        res.x = o[i][0] * inv;
        res.y = o[i][1] * inv;
        res.z = o[i][2] * inv;
        res.w = o[i][3] * inv;
        *(float4*)&outp[(size_t)(b * T_SEQ + m0 + r) * DIMC + h * DH + tx * 4] = res;
    }
}

// ============================================================================
// Fused residual + LayerNorm: out = LN(x + proj_c + proj_ac) * gamma + beta
// one block per row (B*T rows), 256 threads, 3 elems/thread (768/256).
// ============================================================================
__global__ void residual_ln(const float* __restrict__ x,
                            const float* __restrict__ pc,
                            const float* __restrict__ pac,
                            const float* __restrict__ gamma,
                            const float* __restrict__ beta,
                            float* __restrict__ out)
{
    const int row = blockIdx.x;
    const size_t base = (size_t)row * DIMC;
    const int t = threadIdx.x;

    __shared__ float red[256];

    float y[3];
    float s = 0.0f;
#pragma unroll
    for (int i = 0; i < 3; i++) {
        int c = t + i * 256;
        y[i] = x[base + c] + pc[base + c] + pac[base + c];
        s += y[i];
    }
    red[t] = s;
    __syncthreads();
    for (int off = 128; off > 0; off >>= 1) {
        if (t < off) red[t] += red[t + off];
        __syncthreads();
    }
    float mu = red[0] * (1.0f / DIMC);
    __syncthreads();

    float vs = 0.0f;
#pragma unroll
    for (int i = 0; i < 3; i++) {
        float d = y[i] - mu;
        vs += d * d;
    }
    red[t] = vs;
    __syncthreads();
    for (int off = 128; off > 0; off >>= 1) {
        if (t < off) red[t] += red[t + off];
        __syncthreads();
    }
    float inv = rsqrtf(red[0] * (1.0f / DIMC) + 1e-5f);

#pragma unroll
    for (int i = 0; i < 3; i++) {
        int c = t + i * 256;
        out[base + c] = (y[i] - mu) * inv * gamma[c] + beta[c];
    }
}

// ============================================================================
// launch
// ============================================================================
extern "C" void kernel_launch(void* const* d_in, const int* in_sizes, int n_in,
                              void* d_out, int out_size)
{
    const float* x       = (const float*)d_in[0];
    const float* Wqkv_c  = (const float*)d_in[1];
    const float* bqkv_c  = (const float*)d_in[2];
    const float* Wp_c    = (const float*)d_in[3];
    const float* bp_c    = (const float*)d_in[4];
    const float* Wqkv_ac = (const float*)d_in[5];
    const float* bqkv_ac = (const float*)d_in[6];
    const float* Wp_ac   = (const float*)d_in[7];
    const float* bp_ac   = (const float*)d_in[8];
    const float* gamma   = (const float*)d_in[9];
    const float* beta    = (const float*)d_in[10];
    float* out = (float*)d_out;

    float* scratch = nullptr;
    cudaGetSymbolAddress((void**)&scratch, g_scratch);
    float* qkv_c   = scratch;
    float* qkv_ac  = qkv_c  + (size_t)NROWS * QKV_N;
    float* attn_c  = qkv_ac + (size_t)NROWS * QKV_N;
    float* attn_ac = attn_c + (size_t)NROWS * DIMC;
    float* proj_c  = attn_ac + (size_t)NROWS * DIMC;
    float* proj_ac = proj_c + (size_t)NROWS * DIMC;

    dim3 blk(256);

    // QKV GEMMs: [4096, 768] @ [768, 2304]
    sgemm_bias<<<dim3(QKV_N / GT, NROWS / GT), blk>>>(x, Wqkv_c,  bqkv_c,  qkv_c,  NROWS, QKV_N, DIMC);
    sgemm_bias<<<dim3(QKV_N / GT, NROWS / GT), blk>>>(x, Wqkv_ac, bqkv_ac, qkv_ac, NROWS, QKV_N, DIMC);

    // attention (causal / anti-causal)
    attn_kernel<<<dim3(T_SEQ / ABM, NH, B_SZ), blk>>>(qkv_c,  attn_c,  1);
    attn_kernel<<<dim3(T_SEQ / ABM, NH, B_SZ), blk>>>(qkv_ac, attn_ac, 0);

    // projection GEMMs: [4096, 768] @ [768, 768]
    sgemm_bias<<<dim3(DIMC / GT, NROWS / GT), blk>>>(attn_c,  Wp_c,  bp_c,  proj_c,  NROWS, DIMC, DIMC);
    sgemm_bias<<<dim3(DIMC / GT, NROWS / GT), blk>>>(attn_ac, Wp_ac, bp_ac, proj_ac, NROWS, DIMC, DIMC);

    // fused residual + layernorm
    residual_ln<<<NROWS, blk>>>(x, proj_c, proj_ac, gamma, beta, out);
}

// round 3
// speedup vs baseline: 1.3220x; 1.3220x over previous
#include <cuda_runtime.h>
#include <cuda_bf16.h>
#include <math.h>
#include <stdint.h>

#define B_SZ   4
#define T_SEQ  1024
#define DIMC   768
#define NH     12
#define DH     64
#define NROWS  (B_SZ * T_SEQ)          // 4096
#define QKV_N  (3 * DIMC)              // 2304
#define KDIM   768

// ============================================================================
// Scratch (static device globals; no allocation)
// ============================================================================
__device__ float g_qkv_c [(size_t)NROWS * QKV_N];
__device__ float g_qkv_ac[(size_t)NROWS * QKV_N];
__device__ float g_attn_c [(size_t)NROWS * DIMC];
__device__ float g_attn_ac[(size_t)NROWS * DIMC];
__device__ float g_proj_c [(size_t)NROWS * DIMC];
__device__ float g_proj_ac[(size_t)NROWS * DIMC];

// ============================================================================
// tf32 helpers
// ============================================================================
__device__ __forceinline__ uint32_t f32_to_tf32(float f) {
    uint32_t r;
    asm("cvt.rna.tf32.f32 %0, %1;" : "=r"(r) : "f"(f));
    return r;
}

__device__ __forceinline__ void mma_tf32(float& d0, float& d1, float& d2, float& d3,
                                         uint32_t a0, uint32_t a1, uint32_t a2, uint32_t a3,
                                         uint32_t b0, uint32_t b1) {
    asm volatile(
        "mma.sync.aligned.m16n8k8.row.col.f32.tf32.tf32.f32 "
        "{%0,%1,%2,%3}, {%4,%5,%6,%7}, {%8,%9}, {%0,%1,%2,%3};"
        : "+f"(d0), "+f"(d1), "+f"(d2), "+f"(d3)
        : "r"(a0), "r"(a1), "r"(a2), "r"(a3), "r"(b0), "r"(b1));
}

// ============================================================================
// tf32 tensor-core GEMM: C[M,N] = A[M,K] @ W[K,N] + bias[N]
// Block tile 128x128, BK=16, 256 threads (8 warps; warp tile 32x64).
// Double-buffered smem, pad-20 rows (conflict-free fragment loads).
// ============================================================================
#define BM 128
#define BN 128
#define BK 16
#define PADW 20

__global__ void __launch_bounds__(256, 1) gemm_tf32(
    const float* __restrict__ A, const float* __restrict__ W,
    const float* __restrict__ bias, float* __restrict__ C,
    int M, int N, int K)
{
    __shared__ uint32_t As[2][BM][PADW];   // As[st][m][k]
    __shared__ uint32_t Bs[2][BN][PADW];   // Bs[st][n][k]

    const int tid  = threadIdx.x;
    const int lane = tid & 31;
    const int warp = tid >> 5;
    const int wm   = warp & 3;             // 0..3 -> m offset 32*wm
    const int wn   = warp >> 2;            // 0..1 -> n offset 64*wn
    const int lrow = lane >> 2;            // 0..7
    const int lcol = lane & 3;             // 0..3

    const int m0 = blockIdx.y * BM;
    const int n0 = blockIdx.x * BN;

    float acc[2][8][4];
#pragma unroll
    for (int i = 0; i < 2; i++)
#pragma unroll
        for (int j = 0; j < 8; j++)
#pragma unroll
            for (int v = 0; v < 4; v++) acc[i][j][v] = 0.0f;

    const int nk = K / BK;

    // ---- global tile load -> regs (tf32-converted) ----
    // A: 2 float4 per thread; B: 2 float4 per thread
    float4 la[2], lb[2];
    auto load_global = [&](int kb) {
        const int k0 = kb * BK;
#pragma unroll
        for (int i = 0; i < 2; i++) {
            int idx = tid + i * 256;
            int r   = idx >> 2;             // 0..127
            int kc  = (idx & 3) * 4;        // 0,4,8,12
            la[i] = *(const float4*)&A[(size_t)(m0 + r) * K + k0 + kc];
            int kr = idx >> 5;              // 0..15
            int nc = (idx & 31) * 4;        // 0..124
            lb[i] = *(const float4*)&W[(size_t)(k0 + kr) * N + n0 + nc];
        }
    };
    auto store_smem = [&](int st) {
#pragma unroll
        for (int i = 0; i < 2; i++) {
            int idx = tid + i * 256;
            int r   = idx >> 2;
            int kc  = (idx & 3) * 4;
            As[st][r][kc + 0] = f32_to_tf32(la[i].x);
            As[st][r][kc + 1] = f32_to_tf32(la[i].y);
            As[st][r][kc + 2] = f32_to_tf32(la[i].z);
            As[st][r][kc + 3] = f32_to_tf32(la[i].w);
            int kr = idx >> 5;
            int nc = (idx & 31) * 4;
            Bs[st][nc + 0][kr] = f32_to_tf32(lb[i].x);
            Bs[st][nc + 1][kr] = f32_to_tf32(lb[i].y);
            Bs[st][nc + 2][kr] = f32_to_tf32(lb[i].z);
            Bs[st][nc + 3][kr] = f32_to_tf32(lb[i].w);
        }
    };

    load_global(0);
    store_smem(0);
    __syncthreads();

    for (int kb = 0; kb < nk; kb++) {
        const int st = kb & 1;
        if (kb + 1 < nk) load_global(kb + 1);

        // compute from smem[st]
#pragma unroll
        for (int ks = 0; ks < 2; ks++) {
            const int kk = ks * 8;
            uint32_t af[2][4];
#pragma unroll
            for (int mt = 0; mt < 2; mt++) {
                int r = wm * 32 + mt * 16 + lrow;
                af[mt][0] = As[st][r][kk + lcol];
                af[mt][1] = As[st][r + 8][kk + lcol];
                af[mt][2] = As[st][r][kk + lcol + 4];
                af[mt][3] = As[st][r + 8][kk + lcol + 4];
            }
#pragma unroll
            for (int nt = 0; nt < 8; nt++) {
                int n = wn * 64 + nt * 8 + lrow;
                uint32_t b0 = Bs[st][n][kk + lcol];
                uint32_t b1 = Bs[st][n][kk + lcol + 4];
#pragma unroll
                for (int mt = 0; mt < 2; mt++) {
                    mma_tf32(acc[mt][nt][0], acc[mt][nt][1], acc[mt][nt][2], acc[mt][nt][3],
                             af[mt][0], af[mt][1], af[mt][2], af[mt][3], b0, b1);
                }
            }
        }

        __syncthreads();
        if (kb + 1 < nk) {
            store_smem(st ^ 1);
            __syncthreads();
        }
    }

    // ---- epilogue: D mapping d0:[r, c] d1:[r, c+1] d2:[r+8, c] d3:[r+8, c+1]
#pragma unroll
    for (int mt = 0; mt < 2; mt++) {
        int r = m0 + wm * 32 + mt * 16 + lrow;
#pragma unroll
        for (int nt = 0; nt < 8; nt++) {
            int c = n0 + wn * 64 + nt * 8 + lcol * 2;
            float2 bv = *(const float2*)&bias[c];
            float2 o0, o1;
            o0.x = acc[mt][nt][0] + bv.x;
            o0.y = acc[mt][nt][1] + bv.y;
            o1.x = acc[mt][nt][2] + bv.x;
            o1.y = acc[mt][nt][3] + bv.y;
            *(float2*)&C[(size_t)r * N + c]       = o0;
            *(float2*)&C[(size_t)(r + 8) * N + c] = o1;
        }
    }
}

// ============================================================================
// Flash-style masked attention (unchanged)
// ============================================================================
#define ABM 64
#define ABN 32
#define QPAD (DH + 4)

__global__ void attn_kernel(const float* __restrict__ qkv,
                            float* __restrict__ outp,
                            int causal)
{
    __shared__ float Qs[ABM][QPAD];
    __shared__ float Ks[ABN][QPAD];
    __shared__ float Vs[ABN][QPAD];
    __shared__ float Ss[ABM][ABN + 1];
    __shared__ float m_row[ABM], l_row[ABM], sc_row[ABM];

    const int b  = blockIdx.z;
    const int h  = blockIdx.y;
    const int m0 = blockIdx.x * ABM;
    const int tid = threadIdx.x;
    const int tx = tid & 15;
    const int ty = tid >> 4;

    const size_t rowstride = QKV_N;
    const float* qbase = qkv + (size_t)b * T_SEQ * QKV_N + h * DH;
    const float* kbase = qbase + DIMC;
    const float* vbase = qbase + 2 * DIMC;

#pragma unroll
    for (int i = 0; i < 4; i++) {
        int idx = i * 256 + tid;
        int r  = idx >> 4;
        int d4 = (idx & 15) * 4;
        float4 q = *(const float4*)&qbase[(size_t)(m0 + r) * rowstride + d4];
        Qs[r][d4 + 0] = q.x * 0.125f;
        Qs[r][d4 + 1] = q.y * 0.125f;
        Qs[r][d4 + 2] = q.z * 0.125f;
        Qs[r][d4 + 3] = q.w * 0.125f;
    }
    if (tid < ABM) { m_row[tid] = -INFINITY; l_row[tid] = 0.0f; }
    __syncthreads();

    float o[4][4] = {};

    int n_start, n_end;
    if (causal) { n_start = 0;  n_end = m0 + ABM; }
    else        { n_start = m0; n_end = T_SEQ;    }

    for (int n0 = n_start; n0 < n_end; n0 += ABN) {
#pragma unroll
        for (int i = 0; i < 2; i++) {
            int idx = i * 256 + tid;
            int r  = idx >> 4;
            int d4 = (idx & 15) * 4;
            *(float4*)&Ks[r][d4] = *(const float4*)&kbase[(size_t)(n0 + r) * rowstride + d4];
            *(float4*)&Vs[r][d4] = *(const float4*)&vbase[(size_t)(n0 + r) * rowstride + d4];
        }
        __syncthreads();

        float s[4][2] = {};
#pragma unroll
        for (int d = 0; d < DH; d += 4) {
            float4 k0v = *(float4*)&Ks[tx * 2 + 0][d];
            float4 k1v = *(float4*)&Ks[tx * 2 + 1][d];
#pragma unroll
            for (int i = 0; i < 4; i++) {
                float4 qv = *(float4*)&Qs[ty * 4 + i][d];
                s[i][0] += qv.x * k0v.x + qv.y * k0v.y + qv.z * k0v.z + qv.w * k0v.w;
                s[i][1] += qv.x * k1v.x + qv.y * k1v.y + qv.z * k1v.z + qv.w * k1v.w;
            }
        }
#pragma unroll
        for (int i = 0; i < 4; i++) {
            int gq = m0 + ty * 4 + i;
#pragma unroll
            for (int j = 0; j < 2; j++) {
                int gk = n0 + tx * 2 + j;
                bool ok = causal ? (gk <= gq) : (gk >= gq);
                Ss[ty * 4 + i][tx * 2 + j] = ok ? s[i][j] : -INFINITY;
            }
        }
        __syncthreads();

        if (tid < ABM) {
            int r = tid;
            float mo = m_row[r];
            float mx = mo;
#pragma unroll
            for (int n = 0; n < ABN; n++) mx = fmaxf(mx, Ss[r][n]);
            float scl, ls = 0.0f;
            if (mx == -INFINITY) {
                scl = 1.0f;
#pragma unroll
                for (int n = 0; n < ABN; n++) Ss[r][n] = 0.0f;
            } else {
                scl = __expf(mo - mx);
#pragma unroll
                for (int n = 0; n < ABN; n++) {
                    float p = __expf(Ss[r][n] - mx);
                    Ss[r][n] = p;
                    ls += p;
                }
            }
            m_row[r]  = mx;
            l_row[r]  = l_row[r] * scl + ls;
            sc_row[r] = scl;
        }
        __syncthreads();

#pragma unroll
        for (int i = 0; i < 4; i++) {
            float scl = sc_row[ty * 4 + i];
            o[i][0] *= scl; o[i][1] *= scl; o[i][2] *= scl; o[i][3] *= scl;
        }
#pragma unroll
        for (int n = 0; n < ABN; n++) {
            float4 v = *(float4*)&Vs[n][tx * 4];
#pragma unroll
            for (int i = 0; i < 4; i++) {
                float p = Ss[ty * 4 + i][n];
                o[i][0] += p * v.x;
                o[i][1] += p * v.y;
                o[i][2] += p * v.z;
                o[i][3] += p * v.w;
            }
        }
        __syncthreads();
    }

#pragma unroll
    for (int i = 0; i < 4; i++) {
        int r = ty * 4 + i;
        float inv = 1.0f / l_row[r];
        float4 res;
        res.x = o[i][0] * inv;
        res.y = o[i][1] * inv;
        res.z = o[i][2] * inv;
        res.w = o[i][3] * inv;
        *(float4*)&outp[(size_t)(b * T_SEQ + m0 + r) * DIMC + h * DH + tx * 4] = res;
    }
}

// ============================================================================
// Fused residual + LayerNorm (unchanged)
// ============================================================================
__global__ void residual_ln(const float* __restrict__ x,
                            const float* __restrict__ pc,
                            const float* __restrict__ pac,
                            const float* __restrict__ gamma,
                            const float* __restrict__ beta,
                            float* __restrict__ out)
{
    const int row = blockIdx.x;
    const size_t base = (size_t)row * DIMC;
    const int t = threadIdx.x;

    __shared__ float red[256];

    float y[3];
    float s = 0.0f;
#pragma unroll
    for (int i = 0; i < 3; i++) {
        int c = t + i * 256;
        y[i] = x[base + c] + pc[base + c] + pac[base + c];
        s += y[i];
    }
    red[t] = s;
    __syncthreads();
    for (int off = 128; off > 0; off >>= 1) {
        if (t < off) red[t] += red[t + off];
        __syncthreads();
    }
    float mu = red[0] * (1.0f / DIMC);
    __syncthreads();

    float vs = 0.0f;
#pragma unroll
    for (int i = 0; i < 3; i++) {
        float d = y[i] - mu;
        vs += d * d;
    }
    red[t] = vs;
    __syncthreads();
    for (int off = 128; off > 0; off >>= 1) {
        if (t < off) red[t] += red[t + off];
        __syncthreads();
    }
    float inv = rsqrtf(red[0] * (1.0f / DIMC) + 1e-5f);

#pragma unroll
    for (int i = 0; i < 3; i++) {
        int c = t + i * 256;
        out[base + c] = (y[i] - mu) * inv * gamma[c] + beta[c];
    }
}

// ============================================================================
// launch
// ============================================================================
extern "C" void kernel_launch(void* const* d_in, const int* in_sizes, int n_in,
                              void* d_out, int out_size)
{
    const float* x       = (const float*)d_in[0];
    const float* Wqkv_c  = (const float*)d_in[1];
    const float* bqkv_c  = (const float*)d_in[2];
    const float* Wp_c    = (const float*)d_in[3];
    const float* bp_c    = (const float*)d_in[4];
    const float* Wqkv_ac = (const float*)d_in[5];
    const float* bqkv_ac = (const float*)d_in[6];
    const float* Wp_ac   = (const float*)d_in[7];
    const float* bp_ac   = (const float*)d_in[8];
    const float* gamma   = (const float*)d_in[9];
    const float* beta    = (const float*)d_in[10];
    float* out = (float*)d_out;

    float *qkv_c, *qkv_ac, *attn_c, *attn_ac, *proj_c, *proj_ac;
    cudaGetSymbolAddress((void**)&qkv_c,  g_qkv_c);
    cudaGetSymbolAddress((void**)&qkv_ac, g_qkv_ac);
    cudaGetSymbolAddress((void**)&attn_c,  g_attn_c);
    cudaGetSymbolAddress((void**)&attn_ac, g_attn_ac);
    cudaGetSymbolAddress((void**)&proj_c,  g_proj_c);
    cudaGetSymbolAddress((void**)&proj_ac, g_proj_ac);

    dim3 blk256(256);

    // ---- QKV GEMMs (tf32 tensor cores): [4096,768] @ [768,2304] ----
    gemm_tf32<<<dim3(QKV_N / BN, NROWS / BM), blk256>>>(x, Wqkv_c,  bqkv_c,  qkv_c,  NROWS, QKV_N, KDIM);
    gemm_tf32<<<dim3(QKV_N / BN, NROWS / BM), blk256>>>(x, Wqkv_ac, bqkv_ac, qkv_ac, NROWS, QKV_N, KDIM);

    // ---- attention ----
    attn_kernel<<<dim3(T_SEQ / ABM, NH, B_SZ), blk256>>>(qkv_c,  attn_c,  1);
    attn_kernel<<<dim3(T_SEQ / ABM, NH, B_SZ), blk256>>>(qkv_ac, attn_ac, 0);

    // ---- proj GEMMs: [4096,768] @ [768,768] ----
    gemm_tf32<<<dim3(DIMC / BN, NROWS / BM), blk256>>>(attn_c,  Wp_c,  bp_c,  proj_c,  NROWS, DIMC, KDIM);
    gemm_tf32<<<dim3(DIMC / BN, NROWS / BM), blk256>>>(attn_ac, Wp_ac, bp_ac, proj_ac, NROWS, DIMC, KDIM);

    // ---- fused residual + layernorm ----
    residual_ln<<<NROWS, blk256>>>(x, proj_c, proj_ac, gamma, beta, out);
}

// round 4
// speedup vs baseline: 2.1520x; 1.6278x over previous
#include <cuda_runtime.h>
#include <cuda_bf16.h>
#include <math.h>
#include <stdint.h>

#define B_SZ   4
#define T_SEQ  1024
#define DIMC   768
#define NH     12
#define DH     64
#define NROWS  (B_SZ * T_SEQ)          // 4096
#define QKV_N  (3 * DIMC)              // 2304
#define KDIM   768

// ============================================================================
// Scratch (static device globals; no allocation)
// ============================================================================
__device__ float g_qkv_c [(size_t)NROWS * QKV_N];
__device__ float g_qkv_ac[(size_t)NROWS * QKV_N];
__device__ float g_attn_c [(size_t)NROWS * DIMC];
__device__ float g_attn_ac[(size_t)NROWS * DIMC];
__device__ float g_proj_c [(size_t)NROWS * DIMC];
__device__ float g_proj_ac[(size_t)NROWS * DIMC];

// ============================================================================
// tf32 helpers
// ============================================================================
__device__ __forceinline__ uint32_t f32_to_tf32(float f) {
    uint32_t r;
    asm("cvt.rna.tf32.f32 %0, %1;" : "=r"(r) : "f"(f));
    return r;
}

__device__ __forceinline__ void mma_tf32(float& d0, float& d1, float& d2, float& d3,
                                         uint32_t a0, uint32_t a1, uint32_t a2, uint32_t a3,
                                         uint32_t b0, uint32_t b1) {
    asm volatile(
        "mma.sync.aligned.m16n8k8.row.col.f32.tf32.tf32.f32 "
        "{%0,%1,%2,%3}, {%4,%5,%6,%7}, {%8,%9}, {%0,%1,%2,%3};"
        : "+f"(d0), "+f"(d1), "+f"(d2), "+f"(d3)
        : "r"(a0), "r"(a1), "r"(a2), "r"(a3), "r"(b0), "r"(b1));
}

// ============================================================================
// tf32 tensor-core GEMM: C[M,N] = A[M,K] @ W[K,N] + bias[N]  (unchanged)
// ============================================================================
#define BM 128
#define BN 128
#define BK 16
#define PADW 20

__global__ void __launch_bounds__(256, 1) gemm_tf32(
    const float* __restrict__ A, const float* __restrict__ W,
    const float* __restrict__ bias, float* __restrict__ C,
    int M, int N, int K)
{
    __shared__ uint32_t As[2][BM][PADW];
    __shared__ uint32_t Bs[2][BN][PADW];

    const int tid  = threadIdx.x;
    const int lane = tid & 31;
    const int warp = tid >> 5;
    const int wm   = warp & 3;
    const int wn   = warp >> 2;
    const int lrow = lane >> 2;
    const int lcol = lane & 3;

    const int m0 = blockIdx.y * BM;
    const int n0 = blockIdx.x * BN;

    float acc[2][8][4];
#pragma unroll
    for (int i = 0; i < 2; i++)
#pragma unroll
        for (int j = 0; j < 8; j++)
#pragma unroll
            for (int v = 0; v < 4; v++) acc[i][j][v] = 0.0f;

    const int nk = K / BK;

    float4 la[2], lb[2];
    auto load_global = [&](int kb) {
        const int k0 = kb * BK;
#pragma unroll
        for (int i = 0; i < 2; i++) {
            int idx = tid + i * 256;
            int r   = idx >> 2;
            int kc  = (idx & 3) * 4;
            la[i] = *(const float4*)&A[(size_t)(m0 + r) * K + k0 + kc];
            int kr = idx >> 5;
            int nc = (idx & 31) * 4;
            lb[i] = *(const float4*)&W[(size_t)(k0 + kr) * N + n0 + nc];
        }
    };
    auto store_smem = [&](int st) {
#pragma unroll
        for (int i = 0; i < 2; i++) {
            int idx = tid + i * 256;
            int r   = idx >> 2;
            int kc  = (idx & 3) * 4;
            As[st][r][kc + 0] = f32_to_tf32(la[i].x);
            As[st][r][kc + 1] = f32_to_tf32(la[i].y);
            As[st][r][kc + 2] = f32_to_tf32(la[i].z);
            As[st][r][kc + 3] = f32_to_tf32(la[i].w);
            int kr = idx >> 5;
            int nc = (idx & 31) * 4;
            Bs[st][nc + 0][kr] = f32_to_tf32(lb[i].x);
            Bs[st][nc + 1][kr] = f32_to_tf32(lb[i].y);
            Bs[st][nc + 2][kr] = f32_to_tf32(lb[i].z);
            Bs[st][nc + 3][kr] = f32_to_tf32(lb[i].w);
        }
    };

    load_global(0);
    store_smem(0);
    __syncthreads();

    for (int kb = 0; kb < nk; kb++) {
        const int st = kb & 1;
        if (kb + 1 < nk) load_global(kb + 1);

#pragma unroll
        for (int ks = 0; ks < 2; ks++) {
            const int kk = ks * 8;
            uint32_t af[2][4];
#pragma unroll
            for (int mt = 0; mt < 2; mt++) {
                int r = wm * 32 + mt * 16 + lrow;
                af[mt][0] = As[st][r][kk + lcol];
                af[mt][1] = As[st][r + 8][kk + lcol];
                af[mt][2] = As[st][r][kk + lcol + 4];
                af[mt][3] = As[st][r + 8][kk + lcol + 4];
            }
#pragma unroll
            for (int nt = 0; nt < 8; nt++) {
                int n = wn * 64 + nt * 8 + lrow;
                uint32_t b0 = Bs[st][n][kk + lcol];
                uint32_t b1 = Bs[st][n][kk + lcol + 4];
#pragma unroll
                for (int mt = 0; mt < 2; mt++) {
                    mma_tf32(acc[mt][nt][0], acc[mt][nt][1], acc[mt][nt][2], acc[mt][nt][3],
                             af[mt][0], af[mt][1], af[mt][2], af[mt][3], b0, b1);
                }
            }
        }

        __syncthreads();
        if (kb + 1 < nk) {
            store_smem(st ^ 1);
            __syncthreads();
        }
    }

#pragma unroll
    for (int mt = 0; mt < 2; mt++) {
        int r = m0 + wm * 32 + mt * 16 + lrow;
#pragma unroll
        for (int nt = 0; nt < 8; nt++) {
            int c = n0 + wn * 64 + nt * 8 + lcol * 2;
            float2 bv = *(const float2*)&bias[c];
            float2 o0, o1;
            o0.x = acc[mt][nt][0] + bv.x;
            o0.y = acc[mt][nt][1] + bv.y;
            o1.x = acc[mt][nt][2] + bv.x;
            o1.y = acc[mt][nt][3] + bv.y;
            *(float2*)&C[(size_t)r * N + c]       = o0;
            *(float2*)&C[(size_t)(r + 8) * N + c] = o1;
        }
    }
}

// ============================================================================
// Tensor-core flash attention (tf32 mma.sync), both branches in one launch.
// BM=64 query rows per block, BN=64 keys per tile, 128 threads (4 warps).
// Warp w owns rows m0+16w..m0+16w+15. Q fragments persist in registers.
// Smem strides chosen for conflict-free fragment LDS:
//   Ks stride 68 (bank = 4*lrow+lcol), Vs stride 72 (bank = 8*lcol+lrow),
//   Ps stride 68.
// ============================================================================
#define AT_BM 64
#define AT_BN 64
#define KSTR 68
#define VSTR 72
#define PSTR 68
#define AT_SMEM ((64 * KSTR + 64 * VSTR + 64 * PSTR) * 4)   // 53248 B

__global__ void __launch_bounds__(128) attn_mma(
    const float* __restrict__ qkv_c, const float* __restrict__ qkv_ac,
    float* __restrict__ out_c, float* __restrict__ out_ac)
{
    extern __shared__ uint32_t asmem[];
    uint32_t* Ks = asmem;                 // [64][KSTR] tf32
    uint32_t* Vs = Ks + 64 * KSTR;        // [64][VSTR] tf32
    uint32_t* Ps = Vs + 64 * VSTR;        // [64][PSTR] tf32 (Q staging, then P)

    const int causal = (blockIdx.z < 4);
    const int b  = blockIdx.z & 3;
    const int h  = blockIdx.y;
    const int m0 = blockIdx.x * AT_BM;
    const float* qkv = causal ? qkv_c : qkv_ac;
    float* outp      = causal ? out_c : out_ac;

    const int tid  = threadIdx.x;
    const int warp = tid >> 5;
    const int lane = tid & 31;
    const int lrow = lane >> 2;
    const int lcol = lane & 3;

    const float* qbase = qkv + (size_t)b * T_SEQ * QKV_N + h * DH;
    const float* kbase = qbase + DIMC;
    const float* vbase = qbase + 2 * DIMC;

    // ---- stage Q rows into Ps (raw f32), then read warp fragments ----
#pragma unroll
    for (int i = 0; i < 8; i++) {
        int idx = i * 128 + tid;
        int r = idx >> 4, c4 = (idx & 15) * 4;
        float4 q = *(const float4*)&qbase[(size_t)(m0 + r) * QKV_N + c4];
        float* p = (float*)&Ps[r * PSTR + c4];
        p[0] = q.x; p[1] = q.y; p[2] = q.z; p[3] = q.w;
    }
    __syncthreads();

    uint32_t qa[8][4];
    {
        const float* Pf = (const float*)Ps;
        const int r0 = (warp * 16 + lrow) * PSTR;
        const int r1 = r0 + 8 * PSTR;
#pragma unroll
        for (int kt = 0; kt < 8; kt++) {
            int c = kt * 8 + lcol;
            qa[kt][0] = f32_to_tf32(Pf[r0 + c]     * 0.125f);
            qa[kt][1] = f32_to_tf32(Pf[r1 + c]     * 0.125f);
            qa[kt][2] = f32_to_tf32(Pf[r0 + c + 4] * 0.125f);
            qa[kt][3] = f32_to_tf32(Pf[r1 + c + 4] * 0.125f);
        }
    }
    __syncthreads();

    float o[8][4];
#pragma unroll
    for (int i = 0; i < 8; i++)
#pragma unroll
        for (int j = 0; j < 4; j++) o[i][j] = 0.0f;
    float mr0 = -INFINITY, mr1 = -INFINITY, l0 = 0.0f, l1 = 0.0f;

    const int r0g = m0 + warp * 16 + lrow;
    const int r1g = r0g + 8;

    const int n_start = causal ? 0 : m0;
    const int n_end   = causal ? (m0 + AT_BM) : T_SEQ;

    for (int n0 = n_start; n0 < n_end; n0 += AT_BN) {
        // ---- load K, V tiles to smem (pre-converted tf32) ----
#pragma unroll
        for (int i = 0; i < 8; i++) {
            int idx = i * 128 + tid;
            int r = idx >> 4, c4 = (idx & 15) * 4;
            float4 kv = *(const float4*)&kbase[(size_t)(n0 + r) * QKV_N + c4];
            uint32_t* kp = &Ks[r * KSTR + c4];
            kp[0] = f32_to_tf32(kv.x); kp[1] = f32_to_tf32(kv.y);
            kp[2] = f32_to_tf32(kv.z); kp[3] = f32_to_tf32(kv.w);
            float4 vv = *(const float4*)&vbase[(size_t)(n0 + r) * QKV_N + c4];
            uint32_t* vp = &Vs[r * VSTR + c4];
            vp[0] = f32_to_tf32(vv.x); vp[1] = f32_to_tf32(vv.y);
            vp[2] = f32_to_tf32(vv.z); vp[3] = f32_to_tf32(vv.w);
        }
        __syncthreads();

        // ---- S = Q K^T ----
        float s[8][4];
#pragma unroll
        for (int nt = 0; nt < 8; nt++) {
            s[nt][0] = s[nt][1] = s[nt][2] = s[nt][3] = 0.0f;
            const int kr = (nt * 8 + lrow) * KSTR;
#pragma unroll
            for (int kt = 0; kt < 8; kt++) {
                uint32_t b0 = Ks[kr + kt * 8 + lcol];
                uint32_t b1 = Ks[kr + kt * 8 + lcol + 4];
                mma_tf32(s[nt][0], s[nt][1], s[nt][2], s[nt][3],
                         qa[kt][0], qa[kt][1], qa[kt][2], qa[kt][3], b0, b1);
            }
        }

        // ---- mask (warp-uniform skip for interior tiles) ----
        const bool need_mask = causal ? (n0 + AT_BN - 1 > m0 + warp * 16)
                                      : (n0 < m0 + warp * 16 + 15);
        if (need_mask) {
#pragma unroll
            for (int nt = 0; nt < 8; nt++) {
                int c0 = n0 + nt * 8 + 2 * lcol;
                int c1 = c0 + 1;
                if (causal) {
                    if (c0 > r0g) s[nt][0] = -INFINITY;
                    if (c1 > r0g) s[nt][1] = -INFINITY;
                    if (c0 > r1g) s[nt][2] = -INFINITY;
                    if (c1 > r1g) s[nt][3] = -INFINITY;
                } else {
                    if (c0 < r0g) s[nt][0] = -INFINITY;
                    if (c1 < r0g) s[nt][1] = -INFINITY;
                    if (c0 < r1g) s[nt][2] = -INFINITY;
                    if (c1 < r1g) s[nt][3] = -INFINITY;
                }
            }
        }

        // ---- online softmax (quad shuffles) ----
        float t0 = -INFINITY, t1 = -INFINITY;
#pragma unroll
        for (int nt = 0; nt < 8; nt++) {
            t0 = fmaxf(t0, fmaxf(s[nt][0], s[nt][1]));
            t1 = fmaxf(t1, fmaxf(s[nt][2], s[nt][3]));
        }
        t0 = fmaxf(t0, __shfl_xor_sync(0xffffffff, t0, 1));
        t0 = fmaxf(t0, __shfl_xor_sync(0xffffffff, t0, 2));
        t1 = fmaxf(t1, __shfl_xor_sync(0xffffffff, t1, 1));
        t1 = fmaxf(t1, __shfl_xor_sync(0xffffffff, t1, 2));
        float nm0 = fmaxf(mr0, t0), nm1 = fmaxf(mr1, t1);
        float sc0 = __expf(mr0 - nm0), sc1 = __expf(mr1 - nm1);

        float sum0 = 0.0f, sum1 = 0.0f;
#pragma unroll
        for (int nt = 0; nt < 8; nt++) {
            s[nt][0] = __expf(s[nt][0] - nm0); sum0 += s[nt][0];
            s[nt][1] = __expf(s[nt][1] - nm0); sum0 += s[nt][1];
            s[nt][2] = __expf(s[nt][2] - nm1); sum1 += s[nt][2];
            s[nt][3] = __expf(s[nt][3] - nm1); sum1 += s[nt][3];
        }
        sum0 += __shfl_xor_sync(0xffffffff, sum0, 1);
        sum0 += __shfl_xor_sync(0xffffffff, sum0, 2);
        sum1 += __shfl_xor_sync(0xffffffff, sum1, 1);
        sum1 += __shfl_xor_sync(0xffffffff, sum1, 2);
        l0 = l0 * sc0 + sum0;
        l1 = l1 * sc1 + sum1;
        mr0 = nm0; mr1 = nm1;

#pragma unroll
        for (int nt = 0; nt < 8; nt++) {
            o[nt][0] *= sc0; o[nt][1] *= sc0;
            o[nt][2] *= sc1; o[nt][3] *= sc1;
        }

        // ---- P -> smem (warp-private region, tf32) ----
        {
            const int pr0 = (warp * 16 + lrow) * PSTR;
            const int pr1 = pr0 + 8 * PSTR;
#pragma unroll
            for (int nt = 0; nt < 8; nt++) {
                int c = nt * 8 + 2 * lcol;
                Ps[pr0 + c]     = f32_to_tf32(s[nt][0]);
                Ps[pr0 + c + 1] = f32_to_tf32(s[nt][1]);
                Ps[pr1 + c]     = f32_to_tf32(s[nt][2]);
                Ps[pr1 + c + 1] = f32_to_tf32(s[nt][3]);
            }
        }
        __syncwarp();

        // ---- O += P @ V ----
        {
            const int pr0 = (warp * 16 + lrow) * PSTR;
            const int pr1 = pr0 + 8 * PSTR;
#pragma unroll
            for (int kt = 0; kt < 8; kt++) {
                uint32_t a0 = Ps[pr0 + kt * 8 + lcol];
                uint32_t a1 = Ps[pr1 + kt * 8 + lcol];
                uint32_t a2 = Ps[pr0 + kt * 8 + lcol + 4];
                uint32_t a3 = Ps[pr1 + kt * 8 + lcol + 4];
                const int vr0 = (kt * 8 + lcol) * VSTR;
                const int vr1 = (kt * 8 + lcol + 4) * VSTR;
#pragma unroll
                for (int nt = 0; nt < 8; nt++) {
                    uint32_t b0 = Vs[vr0 + nt * 8 + lrow];
                    uint32_t b1 = Vs[vr1 + nt * 8 + lrow];
                    mma_tf32(o[nt][0], o[nt][1], o[nt][2], o[nt][3],
                             a0, a1, a2, a3, b0, b1);
                }
            }
        }
        __syncthreads();
    }

    // ---- epilogue ----
    float inv0 = 1.0f / l0, inv1 = 1.0f / l1;
    size_t ob = (size_t)(b * T_SEQ + r0g) * DIMC + h * DH;
#pragma unroll
    for (int nt = 0; nt < 8; nt++) {
        int c = nt * 8 + 2 * lcol;
        float2 w0, w1;
        w0.x = o[nt][0] * inv0; w0.y = o[nt][1] * inv0;
        w1.x = o[nt][2] * inv1; w1.y = o[nt][3] * inv1;
        *(float2*)&outp[ob + c]            = w0;
        *(float2*)&outp[ob + 8 * DIMC + c] = w1;
    }
}

// ============================================================================
// Fused residual + LayerNorm (unchanged)
// ============================================================================
__global__ void residual_ln(const float* __restrict__ x,
                            const float* __restrict__ pc,
                            const float* __restrict__ pac,
                            const float* __restrict__ gamma,
                            const float* __restrict__ beta,
                            float* __restrict__ out)
{
    const int row = blockIdx.x;
    const size_t base = (size_t)row * DIMC;
    const int t = threadIdx.x;

    __shared__ float red[256];

    float y[3];
    float s = 0.0f;
#pragma unroll
    for (int i = 0; i < 3; i++) {
        int c = t + i * 256;
        y[i] = x[base + c] + pc[base + c] + pac[base + c];
        s += y[i];
    }
    red[t] = s;
    __syncthreads();
    for (int off = 128; off > 0; off >>= 1) {
        if (t < off) red[t] += red[t + off];
        __syncthreads();
    }
    float mu = red[0] * (1.0f / DIMC);
    __syncthreads();

    float vs = 0.0f;
#pragma unroll
    for (int i = 0; i < 3; i++) {
        float d = y[i] - mu;
        vs += d * d;
    }
    red[t] = vs;
    __syncthreads();
    for (int off = 128; off > 0; off >>= 1) {
        if (t < off) red[t] += red[t + off];
        __syncthreads();
    }
    float inv = rsqrtf(red[0] * (1.0f / DIMC) + 1e-5f);

#pragma unroll
    for (int i = 0; i < 3; i++) {
        int c = t + i * 256;
        out[base + c] = (y[i] - mu) * inv * gamma[c] + beta[c];
    }
}

// ============================================================================
// launch
// ============================================================================
extern "C" void kernel_launch(void* const* d_in, const int* in_sizes, int n_in,
                              void* d_out, int out_size)
{
    const float* x       = (const float*)d_in[0];
    const float* Wqkv_c  = (const float*)d_in[1];
    const float* bqkv_c  = (const float*)d_in[2];
    const float* Wp_c    = (const float*)d_in[3];
    const float* bp_c    = (const float*)d_in[4];
    const float* Wqkv_ac = (const float*)d_in[5];
    const float* bqkv_ac = (const float*)d_in[6];
    const float* Wp_ac   = (const float*)d_in[7];
    const float* bp_ac   = (const float*)d_in[8];
    const float* gamma   = (const float*)d_in[9];
    const float* beta    = (const float*)d_in[10];
    float* out = (float*)d_out;

    float *qkv_c, *qkv_ac, *attn_c, *attn_ac, *proj_c, *proj_ac;
    cudaGetSymbolAddress((void**)&qkv_c,  g_qkv_c);
    cudaGetSymbolAddress((void**)&qkv_ac, g_qkv_ac);
    cudaGetSymbolAddress((void**)&attn_c,  g_attn_c);
    cudaGetSymbolAddress((void**)&attn_ac, g_attn_ac);
    cudaGetSymbolAddress((void**)&proj_c,  g_proj_c);
    cudaGetSymbolAddress((void**)&proj_ac, g_proj_ac);

    cudaFuncSetAttribute(attn_mma, cudaFuncAttributeMaxDynamicSharedMemorySize,
                         AT_SMEM);

    dim3 blk256(256);

    // ---- QKV GEMMs (tf32 tensor cores): [4096,768] @ [768,2304] ----
    gemm_tf32<<<dim3(QKV_N / BN, NROWS / BM), blk256>>>(x, Wqkv_c,  bqkv_c,  qkv_c,  NROWS, QKV_N, KDIM);
    gemm_tf32<<<dim3(QKV_N / BN, NROWS / BM), blk256>>>(x, Wqkv_ac, bqkv_ac, qkv_ac, NROWS, QKV_N, KDIM);

    // ---- attention: both branches in one launch ----
    attn_mma<<<dim3(T_SEQ / AT_BM, NH, 2 * B_SZ), dim3(128), AT_SMEM>>>(
        qkv_c, qkv_ac, attn_c, attn_ac);

    // ---- proj GEMMs: [4096,768] @ [768,768] ----
    gemm_tf32<<<dim3(DIMC / BN, NROWS / BM), blk256>>>(attn_c,  Wp_c,  bp_c,  proj_c,  NROWS, DIMC, KDIM);
    gemm_tf32<<<dim3(DIMC / BN, NROWS / BM), blk256>>>(attn_ac, Wp_ac, bp_ac, proj_ac, NROWS, DIMC, KDIM);

    // ---- fused residual + layernorm ----
    residual_ln<<<NROWS, blk256>>>(x, proj_c, proj_ac, gamma, beta, out);
}

// round 5
// speedup vs baseline: 3.6084x; 1.6768x over previous
#include <cuda_runtime.h>
#include <cuda_bf16.h>
#include <math.h>
#include <stdint.h>

#define B_SZ   4
#define T_SEQ  1024
#define DIMC   768
#define NH     12
#define DH     64
#define NROWS  (B_SZ * T_SEQ)          // 4096
#define QKV_N  (3 * DIMC)              // 2304
#define KDIM   768

// ============================================================================
// Scratch (static device globals; no allocation)
// ============================================================================
__device__ float g_qkv_c [(size_t)NROWS * QKV_N];
__device__ float g_qkv_ac[(size_t)NROWS * QKV_N];
__device__ float g_attn_c [(size_t)NROWS * DIMC];
__device__ float g_attn_ac[(size_t)NROWS * DIMC];
__device__ float g_proj_c [(size_t)NROWS * DIMC];
__device__ float g_proj_ac[(size_t)NROWS * DIMC];

// ============================================================================
// helpers
// ============================================================================
__device__ __forceinline__ uint32_t smem_u32(const void* p) {
    uint32_t a;
    asm("{ .reg .u64 t; cvta.to.shared.u64 t, %1; cvt.u32.u64 %0, t; }" : "=r"(a) : "l"(p));
    return a;
}

__device__ __forceinline__ void cp16(uint32_t dst, const void* src) {
    asm volatile("cp.async.cg.shared.global [%0], [%1], 16;" :: "r"(dst), "l"(src));
}
#define CP_COMMIT() asm volatile("cp.async.commit_group;")

__device__ __forceinline__ uint32_t f32_to_tf32(float f) {
    uint32_t r;
    asm("cvt.rna.tf32.f32 %0, %1;" : "=r"(r) : "f"(f));
    return r;
}

__device__ __forceinline__ void mma_tf32(float& d0, float& d1, float& d2, float& d3,
                                         uint32_t a0, uint32_t a1, uint32_t a2, uint32_t a3,
                                         uint32_t b0, uint32_t b1) {
    asm volatile(
        "mma.sync.aligned.m16n8k8.row.col.f32.tf32.tf32.f32 "
        "{%0,%1,%2,%3}, {%4,%5,%6,%7}, {%8,%9}, {%0,%1,%2,%3};"
        : "+f"(d0), "+f"(d1), "+f"(d2), "+f"(d3)
        : "r"(a0), "r"(a1), "r"(a2), "r"(a3), "r"(b0), "r"(b1));
}

// ============================================================================
// tf32 GEMM, cp.async 3-stage pipeline, batched over z (2 weight sets).
// C[M,N] = A[M,K] @ W[K,N] + bias[N]
// Block tile 128x128, BK=16, 256 threads (8 warps; warp tile 32x64).
// As[s][m][k] stride 20 (f32 raw bits, fed to HMMA as tf32-truncated).
// Bs[s][k][n] stride 132 (no transpose needed for cp.async).
// ============================================================================
#define BM 128
#define BN 128
#define BK 16
#define GSTG 3
#define ASTR 20
#define BSTR 132
#define A_STAGE (BM * ASTR)            // 2560 floats
#define B_STAGE (BK * BSTR)            // 2112 floats
#define GEMM_SMEM ((GSTG * (A_STAGE + B_STAGE)) * 4)   // 56064 B

__global__ void __launch_bounds__(256, 2) gemm_tf32_pipe(
    const float* __restrict__ A0, const float* __restrict__ A1,
    const float* __restrict__ W0, const float* __restrict__ W1,
    const float* __restrict__ bias0, const float* __restrict__ bias1,
    float* __restrict__ C0, float* __restrict__ C1,
    int M, int N, int K)
{
    extern __shared__ float smf[];
    float* Asm = smf;                          // [GSTG][A_STAGE]
    float* Bsm = smf + GSTG * A_STAGE;         // [GSTG][B_STAGE]
    const uint32_t sA = smem_u32(Asm);
    const uint32_t sB = smem_u32(Bsm);

    const int z = blockIdx.z;
    const float* A    = z ? A1 : A0;
    const float* W    = z ? W1 : W0;
    const float* bias = z ? bias1 : bias0;
    float*       C    = z ? C1 : C0;

    const int tid  = threadIdx.x;
    const int lane = tid & 31;
    const int warp = tid >> 5;
    const int wm   = warp & 3;
    const int wn   = warp >> 2;
    const int lrow = lane >> 2;
    const int lcol = lane & 3;

    const int m0 = blockIdx.y * BM;
    const int n0 = blockIdx.x * BN;

    // per-thread load coordinates (2 A chunks, 2 B chunks of 16B each)
    int ar[2], akc[2], bkr[2], bnc[2];
#pragma unroll
    for (int i = 0; i < 2; i++) {
        int c = tid + i * 256;
        ar[i]  = c >> 2;          // 0..127
        akc[i] = (c & 3) * 4;     // 0,4,8,12
        bkr[i] = c >> 5;          // 0..15
        bnc[i] = (c & 31) * 4;    // 0..124
    }

    const int nk = K / BK;

    auto load_stage = [&](int s, int kb) {
        const int k0 = kb * BK;
        const uint32_t aB = sA + (uint32_t)(s * A_STAGE) * 4;
        const uint32_t bB = sB + (uint32_t)(s * B_STAGE) * 4;
#pragma unroll
        for (int i = 0; i < 2; i++) {
            cp16(aB + (uint32_t)(ar[i] * ASTR + akc[i]) * 4,
                 &A[(size_t)(m0 + ar[i]) * K + k0 + akc[i]]);
            cp16(bB + (uint32_t)(bkr[i] * BSTR + bnc[i]) * 4,
                 &W[(size_t)(k0 + bkr[i]) * N + n0 + bnc[i]]);
        }
        CP_COMMIT();
    };

    float acc[2][8][4];
#pragma unroll
    for (int i = 0; i < 2; i++)
#pragma unroll
        for (int j = 0; j < 8; j++)
#pragma unroll
            for (int v = 0; v < 4; v++) acc[i][j][v] = 0.0f;

    load_stage(0, 0);
    load_stage(1, 1);

    for (int kb = 0; kb < nk; kb++) {
        const int s = kb % GSTG;
        if (kb + 1 < nk) asm volatile("cp.async.wait_group 1;");
        else             asm volatile("cp.async.wait_group 0;");
        __syncthreads();

        if (kb + 2 < nk) load_stage((kb + 2) % GSTG, kb + 2);

        const float* As = Asm + s * A_STAGE;
        const float* Bs = Bsm + s * B_STAGE;

#pragma unroll
        for (int ks = 0; ks < 2; ks++) {
            const int kk = ks * 8;
            uint32_t af[2][4];
#pragma unroll
            for (int mt = 0; mt < 2; mt++) {
                int r = wm * 32 + mt * 16 + lrow;
                af[mt][0] = __float_as_uint(As[r * ASTR + kk + lcol]);
                af[mt][1] = __float_as_uint(As[(r + 8) * ASTR + kk + lcol]);
                af[mt][2] = __float_as_uint(As[r * ASTR + kk + lcol + 4]);
                af[mt][3] = __float_as_uint(As[(r + 8) * ASTR + kk + lcol + 4]);
            }
#pragma unroll
            for (int nt = 0; nt < 8; nt++) {
                int n = wn * 64 + nt * 8 + lrow;
                uint32_t b0 = __float_as_uint(Bs[(kk + lcol) * BSTR + n]);
                uint32_t b1 = __float_as_uint(Bs[(kk + lcol + 4) * BSTR + n]);
#pragma unroll
                for (int mt = 0; mt < 2; mt++) {
                    mma_tf32(acc[mt][nt][0], acc[mt][nt][1], acc[mt][nt][2], acc[mt][nt][3],
                             af[mt][0], af[mt][1], af[mt][2], af[mt][3], b0, b1);
                }
            }
        }
        __syncthreads();
    }

    // epilogue
#pragma unroll
    for (int mt = 0; mt < 2; mt++) {
        int r = m0 + wm * 32 + mt * 16 + lrow;
#pragma unroll
        for (int nt = 0; nt < 8; nt++) {
            int c = n0 + wn * 64 + nt * 8 + lcol * 2;
            float2 bv = *(const float2*)&bias[c];
            float2 o0, o1;
            o0.x = acc[mt][nt][0] + bv.x;
            o0.y = acc[mt][nt][1] + bv.y;
            o1.x = acc[mt][nt][2] + bv.x;
            o1.y = acc[mt][nt][3] + bv.y;
            *(float2*)&C[(size_t)r * N + c]       = o0;
            *(float2*)&C[(size_t)(r + 8) * N + c] = o1;
        }
    }
}

// ============================================================================
// Tensor-core flash attention (tf32 mma.sync), both branches in one launch.
// (unchanged from round 4)
// ============================================================================
#define AT_BM 64
#define AT_BN 64
#define KSTR 68
#define VSTR 72
#define PSTR 68
#define AT_SMEM ((64 * KSTR + 64 * VSTR + 64 * PSTR) * 4)   // 53248 B

__global__ void __launch_bounds__(128) attn_mma(
    const float* __restrict__ qkv_c, const float* __restrict__ qkv_ac,
    float* __restrict__ out_c, float* __restrict__ out_ac)
{
    extern __shared__ uint32_t asmem[];
    uint32_t* Ks = asmem;
    uint32_t* Vs = Ks + 64 * KSTR;
    uint32_t* Ps = Vs + 64 * VSTR;

    const int causal = (blockIdx.z < 4);
    const int b  = blockIdx.z & 3;
    const int h  = blockIdx.y;
    const int m0 = blockIdx.x * AT_BM;
    const float* qkv = causal ? qkv_c : qkv_ac;
    float* outp      = causal ? out_c : out_ac;

    const int tid  = threadIdx.x;
    const int warp = tid >> 5;
    const int lane = tid & 31;
    const int lrow = lane >> 2;
    const int lcol = lane & 3;

    const float* qbase = qkv + (size_t)b * T_SEQ * QKV_N + h * DH;
    const float* kbase = qbase + DIMC;
    const float* vbase = qbase + 2 * DIMC;

#pragma unroll
    for (int i = 0; i < 8; i++) {
        int idx = i * 128 + tid;
        int r = idx >> 4, c4 = (idx & 15) * 4;
        float4 q = *(const float4*)&qbase[(size_t)(m0 + r) * QKV_N + c4];
        float* p = (float*)&Ps[r * PSTR + c4];
        p[0] = q.x; p[1] = q.y; p[2] = q.z; p[3] = q.w;
    }
    __syncthreads();

    uint32_t qa[8][4];
    {
        const float* Pf = (const float*)Ps;
        const int r0 = (warp * 16 + lrow) * PSTR;
        const int r1 = r0 + 8 * PSTR;
#pragma unroll
        for (int kt = 0; kt < 8; kt++) {
            int c = kt * 8 + lcol;
            qa[kt][0] = f32_to_tf32(Pf[r0 + c]     * 0.125f);
            qa[kt][1] = f32_to_tf32(Pf[r1 + c]     * 0.125f);
            qa[kt][2] = f32_to_tf32(Pf[r0 + c + 4] * 0.125f);
            qa[kt][3] = f32_to_tf32(Pf[r1 + c + 4] * 0.125f);
        }
    }
    __syncthreads();

    float o[8][4];
#pragma unroll
    for (int i = 0; i < 8; i++)
#pragma unroll
        for (int j = 0; j < 4; j++) o[i][j] = 0.0f;
    float mr0 = -INFINITY, mr1 = -INFINITY, l0 = 0.0f, l1 = 0.0f;

    const int r0g = m0 + warp * 16 + lrow;
    const int r1g = r0g + 8;

    const int n_start = causal ? 0 : m0;
    const int n_end   = causal ? (m0 + AT_BM) : T_SEQ;

    for (int n0 = n_start; n0 < n_end; n0 += AT_BN) {
#pragma unroll
        for (int i = 0; i < 8; i++) {
            int idx = i * 128 + tid;
            int r = idx >> 4, c4 = (idx & 15) * 4;
            float4 kv = *(const float4*)&kbase[(size_t)(n0 + r) * QKV_N + c4];
            uint32_t* kp = &Ks[r * KSTR + c4];
            kp[0] = f32_to_tf32(kv.x); kp[1] = f32_to_tf32(kv.y);
            kp[2] = f32_to_tf32(kv.z); kp[3] = f32_to_tf32(kv.w);
            float4 vv = *(const float4*)&vbase[(size_t)(n0 + r) * QKV_N + c4];
            uint32_t* vp = &Vs[r * VSTR + c4];
            vp[0] = f32_to_tf32(vv.x); vp[1] = f32_to_tf32(vv.y);
            vp[2] = f32_to_tf32(vv.z); vp[3] = f32_to_tf32(vv.w);
        }
        __syncthreads();

        float s[8][4];
#pragma unroll
        for (int nt = 0; nt < 8; nt++) {
            s[nt][0] = s[nt][1] = s[nt][2] = s[nt][3] = 0.0f;
            const int kr = (nt * 8 + lrow) * KSTR;
#pragma unroll
            for (int kt = 0; kt < 8; kt++) {
                uint32_t b0 = Ks[kr + kt * 8 + lcol];
                uint32_t b1 = Ks[kr + kt * 8 + lcol + 4];
                mma_tf32(s[nt][0], s[nt][1], s[nt][2], s[nt][3],
                         qa[kt][0], qa[kt][1], qa[kt][2], qa[kt][3], b0, b1);
            }
        }

        const bool need_mask = causal ? (n0 + AT_BN - 1 > m0 + warp * 16)
                                      : (n0 < m0 + warp * 16 + 15);
        if (need_mask) {
#pragma unroll
            for (int nt = 0; nt < 8; nt++) {
                int c0 = n0 + nt * 8 + 2 * lcol;
                int c1 = c0 + 1;
                if (causal) {
                    if (c0 > r0g) s[nt][0] = -INFINITY;
                    if (c1 > r0g) s[nt][1] = -INFINITY;
                    if (c0 > r1g) s[nt][2] = -INFINITY;
                    if (c1 > r1g) s[nt][3] = -INFINITY;
                } else {
                    if (c0 < r0g) s[nt][0] = -INFINITY;
                    if (c1 < r0g) s[nt][1] = -INFINITY;
                    if (c0 < r1g) s[nt][2] = -INFINITY;
                    if (c1 < r1g) s[nt][3] = -INFINITY;
                }
            }
        }

        float t0 = -INFINITY, t1 = -INFINITY;
#pragma unroll
        for (int nt = 0; nt < 8; nt++) {
            t0 = fmaxf(t0, fmaxf(s[nt][0], s[nt][1]));
            t1 = fmaxf(t1, fmaxf(s[nt][2], s[nt][3]));
        }
        t0 = fmaxf(t0, __shfl_xor_sync(0xffffffff, t0, 1));
        t0 = fmaxf(t0, __shfl_xor_sync(0xffffffff, t0, 2));
        t1 = fmaxf(t1, __shfl_xor_sync(0xffffffff, t1, 1));
        t1 = fmaxf(t1, __shfl_xor_sync(0xffffffff, t1, 2));
        float nm0 = fmaxf(mr0, t0), nm1 = fmaxf(mr1, t1);
        float sc0 = __expf(mr0 - nm0), sc1 = __expf(mr1 - nm1);

        float sum0 = 0.0f, sum1 = 0.0f;
#pragma unroll
        for (int nt = 0; nt < 8; nt++) {
            s[nt][0] = __expf(s[nt][0] - nm0); sum0 += s[nt][0];
            s[nt][1] = __expf(s[nt][1] - nm0); sum0 += s[nt][1];
            s[nt][2] = __expf(s[nt][2] - nm1); sum1 += s[nt][2];
            s[nt][3] = __expf(s[nt][3] - nm1); sum1 += s[nt][3];
        }
        sum0 += __shfl_xor_sync(0xffffffff, sum0, 1);
        sum0 += __shfl_xor_sync(0xffffffff, sum0, 2);
        sum1 += __shfl_xor_sync(0xffffffff, sum1, 1);
        sum1 += __shfl_xor_sync(0xffffffff, sum1, 2);
        l0 = l0 * sc0 + sum0;
        l1 = l1 * sc1 + sum1;
        mr0 = nm0; mr1 = nm1;

#pragma unroll
        for (int nt = 0; nt < 8; nt++) {
            o[nt][0] *= sc0; o[nt][1] *= sc0;
            o[nt][2] *= sc1; o[nt][3] *= sc1;
        }

        {
            const int pr0 = (warp * 16 + lrow) * PSTR;
            const int pr1 = pr0 + 8 * PSTR;
#pragma unroll
            for (int nt = 0; nt < 8; nt++) {
                int c = nt * 8 + 2 * lcol;
                Ps[pr0 + c]     = f32_to_tf32(s[nt][0]);
                Ps[pr0 + c + 1] = f32_to_tf32(s[nt][1]);
                Ps[pr1 + c]     = f32_to_tf32(s[nt][2]);
                Ps[pr1 + c + 1] = f32_to_tf32(s[nt][3]);
            }
        }
        __syncwarp();

        {
            const int pr0 = (warp * 16 + lrow) * PSTR;
            const int pr1 = pr0 + 8 * PSTR;
#pragma unroll
            for (int kt = 0; kt < 8; kt++) {
                uint32_t a0 = Ps[pr0 + kt * 8 + lcol];
                uint32_t a1 = Ps[pr1 + kt * 8 + lcol];
                uint32_t a2 = Ps[pr0 + kt * 8 + lcol + 4];
                uint32_t a3 = Ps[pr1 + kt * 8 + lcol + 4];
                const int vr0 = (kt * 8 + lcol) * VSTR;
                const int vr1 = (kt * 8 + lcol + 4) * VSTR;
#pragma unroll
                for (int nt = 0; nt < 8; nt++) {
                    uint32_t b0 = Vs[vr0 + nt * 8 + lrow];
                    uint32_t b1 = Vs[vr1 + nt * 8 + lrow];
                    mma_tf32(o[nt][0], o[nt][1], o[nt][2], o[nt][3],
                             a0, a1, a2, a3, b0, b1);
                }
            }
        }
        __syncthreads();
    }

    float inv0 = 1.0f / l0, inv1 = 1.0f / l1;
    size_t ob = (size_t)(b * T_SEQ + r0g) * DIMC + h * DH;
#pragma unroll
    for (int nt = 0; nt < 8; nt++) {
        int c = nt * 8 + 2 * lcol;
        float2 w0, w1;
        w0.x = o[nt][0] * inv0; w0.y = o[nt][1] * inv0;
        w1.x = o[nt][2] * inv1; w1.y = o[nt][3] * inv1;
        *(float2*)&outp[ob + c]            = w0;
        *(float2*)&outp[ob + 8 * DIMC + c] = w1;
    }
}

// ============================================================================
// Fused residual + LayerNorm (unchanged)
// ============================================================================
__global__ void residual_ln(const float* __restrict__ x,
                            const float* __restrict__ pc,
                            const float* __restrict__ pac,
                            const float* __restrict__ gamma,
                            const float* __restrict__ beta,
                            float* __restrict__ out)
{
    const int row = blockIdx.x;
    const size_t base = (size_t)row * DIMC;
    const int t = threadIdx.x;

    __shared__ float red[256];

    float y[3];
    float s = 0.0f;
#pragma unroll
    for (int i = 0; i < 3; i++) {
        int c = t + i * 256;
        y[i] = x[base + c] + pc[base + c] + pac[base + c];
        s += y[i];
    }
    red[t] = s;
    __syncthreads();
    for (int off = 128; off > 0; off >>= 1) {
        if (t < off) red[t] += red[t + off];
        __syncthreads();
    }
    float mu = red[0] * (1.0f / DIMC);
    __syncthreads();

    float vs = 0.0f;
#pragma unroll
    for (int i = 0; i < 3; i++) {
        float d = y[i] - mu;
        vs += d * d;
    }
    red[t] = vs;
    __syncthreads();
    for (int off = 128; off > 0; off >>= 1) {
        if (t < off) red[t] += red[t + off];
        __syncthreads();
    }
    float inv = rsqrtf(red[0] * (1.0f / DIMC) + 1e-5f);

#pragma unroll
    for (int i = 0; i < 3; i++) {
        int c = t + i * 256;
        out[base + c] = (y[i] - mu) * inv * gamma[c] + beta[c];
    }
}

// ============================================================================
// launch
// ============================================================================
extern "C" void kernel_launch(void* const* d_in, const int* in_sizes, int n_in,
                              void* d_out, int out_size)
{
    const float* x       = (const float*)d_in[0];
    const float* Wqkv_c  = (const float*)d_in[1];
    const float* bqkv_c  = (const float*)d_in[2];
    const float* Wp_c    = (const float*)d_in[3];
    const float* bp_c    = (const float*)d_in[4];
    const float* Wqkv_ac = (const float*)d_in[5];
    const float* bqkv_ac = (const float*)d_in[6];
    const float* Wp_ac   = (const float*)d_in[7];
    const float* bp_ac   = (const float*)d_in[8];
    const float* gamma   = (const float*)d_in[9];
    const float* beta    = (const float*)d_in[10];
    float* out = (float*)d_out;

    float *qkv_c, *qkv_ac, *attn_c, *attn_ac, *proj_c, *proj_ac;
    cudaGetSymbolAddress((void**)&qkv_c,  g_qkv_c);
    cudaGetSymbolAddress((void**)&qkv_ac, g_qkv_ac);
    cudaGetSymbolAddress((void**)&attn_c,  g_attn_c);
    cudaGetSymbolAddress((void**)&attn_ac, g_attn_ac);
    cudaGetSymbolAddress((void**)&proj_c,  g_proj_c);
    cudaGetSymbolAddress((void**)&proj_ac, g_proj_ac);

    cudaFuncSetAttribute(gemm_tf32_pipe, cudaFuncAttributeMaxDynamicSharedMemorySize,
                         GEMM_SMEM);
    cudaFuncSetAttribute(attn_mma, cudaFuncAttributeMaxDynamicSharedMemorySize,
                         AT_SMEM);

    dim3 blk256(256);

    // ---- QKV GEMMs, both branches in one launch ----
    gemm_tf32_pipe<<<dim3(QKV_N / BN, NROWS / BM, 2), blk256, GEMM_SMEM>>>(
        x, x, Wqkv_c, Wqkv_ac, bqkv_c, bqkv_ac, qkv_c, qkv_ac,
        NROWS, QKV_N, KDIM);

    // ---- attention: both branches in one launch ----
    attn_mma<<<dim3(T_SEQ / AT_BM, NH, 2 * B_SZ), dim3(128), AT_SMEM>>>(
        qkv_c, qkv_ac, attn_c, attn_ac);

    // ---- proj GEMMs, both branches in one launch ----
    gemm_tf32_pipe<<<dim3(DIMC / BN, NROWS / BM, 2), blk256, GEMM_SMEM>>>(
        attn_c, attn_ac, Wp_c, Wp_ac, bp_c, bp_ac, proj_c, proj_ac,
        NROWS, DIMC, KDIM);

    // ---- fused residual + layernorm ----
    residual_ln<<<NROWS, blk256>>>(x, proj_c, proj_ac, gamma, beta, out);
}